// round 2
// baseline (speedup 1.0000x reference)
#include <cuda_runtime.h>
#include <math.h>

#define NH   16
#define HD   64
#define KW   13
#define CDIM 1024
#define BB   4
#define LL   4096
#define QK_SCALE 0.125f   // 64^-0.5
#define RPB_W (2*KW-1)    // 25

// ---------------- scratch (device globals; no allocation allowed) ------------
// q,k,v in [B,H,L,D]; attn out in [B,L,H*D]
__device__ float g_q[(size_t)BB*NH*LL*HD];
__device__ float g_k[(size_t)BB*NH*LL*HD];
__device__ float g_v[(size_t)BB*NH*LL*HD];
__device__ float g_attn[(size_t)BB*LL*CDIM];

// ---------------- SGEMM 128x128x8, 256 thr, 8x8 microtile -------------------
// C[M,N] = A[M,K] * B[K,N]; M,N multiples of 128, K multiple of 8.
// MODE 0: A = x (arg), QKV epilogue (scatter into g_q/g_k/g_v, scale q, +bias)
// MODE 1: A = g_attn (device global), plain epilogue into C with bias

template<int MODE>
__global__ __launch_bounds__(256, 1)
void sgemm_kernel(const float* __restrict__ Aarg, const float* __restrict__ Bm,
                  const float* __restrict__ bias, float* __restrict__ C,
                  int M, int N, int K)
{
    __shared__ float As[8][128];   // transposed A tile
    __shared__ float Bs[8][128];

    const float* __restrict__ A = (MODE == 1) ? (const float*)g_attn : Aarg;

    const int tid = threadIdx.x;
    const int tx  = tid & 15;       // 0..15 (col group)
    const int ty  = tid >> 4;       // 0..15 (row group)
    const int m0  = blockIdx.y * 128;
    const int n0  = blockIdx.x * 128;

    // A-tile load: thread -> (row=tid/2, 4 floats at col (tid&1)*4)
    const int a_row = tid >> 1;
    const int a_col = (tid & 1) * 4;
    // B-tile load: thread -> (row=tid/32, 4 floats at col (tid&31)*4)
    const int b_row = tid >> 5;
    const int b_col = (tid & 31) * 4;

    float acc[8][8];
    #pragma unroll
    for (int i = 0; i < 8; i++)
        #pragma unroll
        for (int j = 0; j < 8; j++) acc[i][j] = 0.f;

    const float* Aptr = A + (size_t)(m0 + a_row) * K + a_col;
    const float* Bptr = Bm + (size_t)b_row * N + n0 + b_col;

    for (int k0 = 0; k0 < K; k0 += 8) {
        float4 av = *(const float4*)(Aptr + k0);
        float4 bv = *(const float4*)(Bptr + (size_t)k0 * N);
        As[a_col + 0][a_row] = av.x;
        As[a_col + 1][a_row] = av.y;
        As[a_col + 2][a_row] = av.z;
        As[a_col + 3][a_row] = av.w;
        *(float4*)&Bs[b_row][b_col] = bv;
        __syncthreads();

        #pragma unroll
        for (int kk = 0; kk < 8; kk++) {
            float a[8], b[8];
            float4 t0 = *(const float4*)&As[kk][ty * 8];
            float4 t1 = *(const float4*)&As[kk][ty * 8 + 4];
            a[0]=t0.x; a[1]=t0.y; a[2]=t0.z; a[3]=t0.w;
            a[4]=t1.x; a[5]=t1.y; a[6]=t1.z; a[7]=t1.w;
            float4 u0 = *(const float4*)&Bs[kk][tx * 8];
            float4 u1 = *(const float4*)&Bs[kk][tx * 8 + 4];
            b[0]=u0.x; b[1]=u0.y; b[2]=u0.z; b[3]=u0.w;
            b[4]=u1.x; b[5]=u1.y; b[6]=u1.z; b[7]=u1.w;
            #pragma unroll
            for (int i = 0; i < 8; i++)
                #pragma unroll
                for (int j = 0; j < 8; j++)
                    acc[i][j] = fmaf(a[i], b[j], acc[i][j]);
        }
        __syncthreads();
    }

    // epilogue
    #pragma unroll
    for (int i = 0; i < 8; i++) {
        const int m = m0 + ty * 8 + i;
        #pragma unroll
        for (int j = 0; j < 8; j++) {
            const int n = n0 + tx * 8 + j;
            float val = acc[i][j] + bias[n];
            if (MODE == 0) {
                const int b_  = m >> 12;        // m / L (L=4096)
                const int l   = m & (LL - 1);
                const int wch = n >> 10;        // 0=q 1=k 2=v
                const int rem = n & 1023;
                const int h   = rem >> 6;
                const int d   = rem & 63;
                const size_t idx = (((size_t)(b_ * NH + h)) * LL + l) * HD + d;
                if (wch == 0)      g_q[idx] = val * QK_SCALE;
                else if (wch == 1) g_k[idx] = val;
                else               g_v[idx] = val;
            } else {
                C[(size_t)m * N + n] = val;
            }
        }
    }
}

// ---------------- NA1D attention ------------------------------------------
// block = 128 queries of one (b,h). Two-phase: K tile -> logits, then the SAME
// smem buffer is reloaded with the V tile (halves smem; fits static 48KB).
#define TROWS 140
#define ROWP  65   // padded row stride to kill bank conflicts

__global__ __launch_bounds__(128, 1)
void na1d_kernel(const float* __restrict__ rpb)
{
    __shared__ float tile[TROWS * ROWP];   // K tile, then V tile
    __shared__ float rsh[RPB_W];

    const int tid = threadIdx.x;
    const int l0  = blockIdx.x * 128;
    const int h   = blockIdx.y;
    const int b   = blockIdx.z;

    const size_t head_base = ((size_t)(b * NH + h)) * LL * HD;
    const int kbase = min(max(l0 - (KW / 2), 0), LL - KW);
    const int krows = min(TROWS, LL - kbase);

    // ---- phase 1: load K tile ----
    const float* kp = g_k + head_base + (size_t)kbase * HD;
    for (int idx = tid; idx < krows * 16; idx += 128) {
        const int r  = idx >> 4;
        const int c4 = (idx & 15) * 4;
        float4 kv = *(const float4*)(kp + (size_t)r * HD + c4);
        float* kd = &tile[r * ROWP + c4];
        kd[0]=kv.x; kd[1]=kv.y; kd[2]=kv.z; kd[3]=kv.w;
    }
    if (tid < RPB_W) rsh[tid] = rpb[h * RPB_W + tid];
    __syncthreads();

    const int l = l0 + tid;
    // load q into registers
    float qreg[HD];
    const float* qp = g_q + head_base + (size_t)l * HD;
    #pragma unroll
    for (int c4 = 0; c4 < 16; c4++) {
        float4 qv = *(const float4*)(qp + c4 * 4);
        qreg[c4*4+0]=qv.x; qreg[c4*4+1]=qv.y; qreg[c4*4+2]=qv.z; qreg[c4*4+3]=qv.w;
    }

    const int ni = min(max(l - (KW / 2), 0), LL - KW);
    const int r0 = ni - kbase;
    const int bias0 = ni - l + (KW - 1);

    float logits[KW];
    #pragma unroll
    for (int kk = 0; kk < KW; kk++) {
        const float* kr = &tile[(r0 + kk) * ROWP];
        float s = 0.f;
        #pragma unroll
        for (int d = 0; d < HD; d++) s = fmaf(qreg[d], kr[d], s);
        logits[kk] = s + rsh[bias0 + kk];
    }

    float mx = logits[0];
    #pragma unroll
    for (int kk = 1; kk < KW; kk++) mx = fmaxf(mx, logits[kk]);
    float ssum = 0.f;
    #pragma unroll
    for (int kk = 0; kk < KW; kk++) { logits[kk] = expf(logits[kk] - mx); ssum += logits[kk]; }
    const float inv = 1.f / ssum;

    // ---- phase 2: reload the same smem with V tile ----
    __syncthreads();
    const float* vp = g_v + head_base + (size_t)kbase * HD;
    for (int idx = tid; idx < krows * 16; idx += 128) {
        const int r  = idx >> 4;
        const int c4 = (idx & 15) * 4;
        float4 vv = *(const float4*)(vp + (size_t)r * HD + c4);
        float* vd = &tile[r * ROWP + c4];
        vd[0]=vv.x; vd[1]=vv.y; vd[2]=vv.z; vd[3]=vv.w;
    }
    __syncthreads();

    float accv[HD];
    #pragma unroll
    for (int d = 0; d < HD; d++) accv[d] = 0.f;
    #pragma unroll
    for (int kk = 0; kk < KW; kk++) {
        const float w = logits[kk] * inv;
        const float* vr = &tile[(r0 + kk) * ROWP];
        #pragma unroll
        for (int d = 0; d < HD; d++) accv[d] = fmaf(w, vr[d], accv[d]);
    }

    // write [B, L, H*D]
    float* op = g_attn + ((size_t)b * LL + l) * CDIM + h * HD;
    #pragma unroll
    for (int c4 = 0; c4 < 16; c4++) {
        float4 ov;
        ov.x = accv[c4*4+0]; ov.y = accv[c4*4+1];
        ov.z = accv[c4*4+2]; ov.w = accv[c4*4+3];
        *(float4*)(op + c4 * 4) = ov;
    }
}

// ---------------- launch ----------------------------------------------------
extern "C" void kernel_launch(void* const* d_in, const int* in_sizes, int n_in,
                              void* d_out, int out_size)
{
    const float* x      = (const float*)d_in[0];
    const float* w_qkv  = (const float*)d_in[1];
    const float* b_qkv  = (const float*)d_in[2];
    const float* rpb    = (const float*)d_in[3];
    const float* w_proj = (const float*)d_in[4];
    const float* b_proj = (const float*)d_in[5];
    float* out = (float*)d_out;

    const int M = BB * LL;          // 16384

    // 1) QKV GEMM: [M,1024] x [1024,3072] -> scatter to g_q/g_k/g_v
    {
        dim3 grid(3 * CDIM / 128, M / 128);
        sgemm_kernel<0><<<grid, 256>>>(x, w_qkv, b_qkv, nullptr, M, 3 * CDIM, CDIM);
    }

    // 2) NA1D attention -> g_attn
    {
        dim3 grid(LL / 128, NH, BB);
        na1d_kernel<<<grid, 128>>>(rpb);
    }

    // 3) proj GEMM: g_attn [M,1024] x [1024,1024] -> d_out
    {
        dim3 grid(CDIM / 128, M / 128);
        sgemm_kernel<1><<<grid, 256>>>(nullptr, w_proj, b_proj, out, M, CDIM, CDIM);
    }
}